// round 15
// baseline (speedup 1.0000x reference)
#include <cuda_runtime.h>
#include <cuda_bf16.h>
#include <cstdint>

// Problem shape
#define MROWS   8192          // B*S
#define NOUT    8192
#define KIN     2048
#define KTILES  32            // KIN / 64
#define TILE_B  16384         // 128 rows * 128 bytes (64 bf16), SW128-swizzled
#define APART   1024          // amax partial blocks per tensor

// Scratch (device globals: allocation-free rule).
// g_part / g_amax_f fully overwritten every call -> stateless across replays.
__device__ unsigned       g_part[2][APART];
__device__ float          g_amax_f[2];
__device__ __nv_bfloat16  g_xq[(size_t)MROWS * KIN]; // tiled+swizzled
__device__ __nv_bfloat16  g_wq[(size_t)NOUT * KIN];  // tiled+swizzled

#define SW128(o) ((o) ^ (((o) >> 3) & 0x70))

__device__ __forceinline__ uint32_t smem_u32(const void* p) {
    uint32_t a;
    asm("{ .reg .u64 t; cvta.to.shared.u64 t, %1; cvt.u32.u64 %0, t; }" : "=r"(a) : "l"(p));
    return a;
}

__device__ __forceinline__ void cp16(uint32_t dst, const void* src) {
    asm volatile("cp.async.cg.shared.global [%0], [%1], 16;" :: "r"(dst), "l"(src) : "memory");
}

// cp.async completion of THIS thread's prior copies -> ONE arrival (noinc)
__device__ __forceinline__ void cpasync_arrive(uint32_t mbar) {
    asm volatile("cp.async.mbarrier.arrive.noinc.shared.b64 [%0];" :: "r"(mbar) : "memory");
}
__device__ __forceinline__ void mbar_init(uint32_t mbar, uint32_t cnt) {
    asm volatile("mbarrier.init.shared.b64 [%0], %1;" :: "r"(mbar), "r"(cnt) : "memory");
}
__device__ __forceinline__ void mbar_wait(uint32_t mbar, uint32_t parity) {
    asm volatile(
        "{\n\t.reg .pred p;\n\t"
        "WL_%=:\n\t"
        "mbarrier.try_wait.parity.shared.b64 p, [%0], %1;\n\t"
        "@!p bra WL_%=;\n\t}"
        :: "r"(mbar), "r"(parity) : "memory");
}

// named-barrier producer/consumer pair (cheap rendezvous)
__device__ __forceinline__ void nbar_arrive(int id) {
    asm volatile("bar.arrive %0, 256;" :: "r"(id) : "memory");
}
__device__ __forceinline__ void nbar_sync(int id) {
    asm volatile("bar.sync %0, 256;" :: "r"(id) : "memory");
}

__device__ __forceinline__ void ldsm_x4(uint32_t& r0, uint32_t& r1, uint32_t& r2, uint32_t& r3,
                                        uint32_t addr) {
    asm volatile("ldmatrix.sync.aligned.m8n8.x4.shared.b16 {%0,%1,%2,%3}, [%4];"
                 : "=r"(r0), "=r"(r1), "=r"(r2), "=r"(r3) : "r"(addr));
}

__device__ __forceinline__ void mma16816(float* c, const uint32_t* a, uint32_t b0, uint32_t b1) {
    asm volatile(
        "mma.sync.aligned.m16n8k16.row.col.f32.bf16.bf16.f32 "
        "{%0,%1,%2,%3}, {%4,%5,%6,%7}, {%8,%9}, {%0,%1,%2,%3};"
        : "+f"(c[0]), "+f"(c[1]), "+f"(c[2]), "+f"(c[3])
        : "r"(a[0]), "r"(a[1]), "r"(a[2]), "r"(a[3]), "r"(b0), "r"(b1));
}

__device__ __forceinline__ unsigned warp_max(unsigned m) {
    #pragma unroll
    for (int o = 16; o; o >>= 1) m = max(m, __shfl_xor_sync(0xFFFFFFFFu, m, o));
    return m;
}
__device__ __forceinline__ unsigned u4max(float4 v) {
    unsigned m = max(__float_as_uint(fabsf(v.x)), __float_as_uint(fabsf(v.y)));
    m = max(m, __float_as_uint(fabsf(v.z)));
    return max(m, __float_as_uint(fabsf(v.w)));
}

// ---------------------------------------------------------------------------
// Stage 1: per-block amax partials for BOTH tensors (blockIdx.y selects).
__global__ void amax2_k(const float4* __restrict__ x, const float4* __restrict__ w, int n4) {
    const float4* src = blockIdx.y ? w : x;
    const int stride = APART * 256;
    int i = blockIdx.x * 256 + threadIdx.x;
    unsigned m0 = 0, m1 = 0, m2 = 0, m3 = 0;
    for (; i + 3 * stride < n4; i += 4 * stride) {
        float4 v0 = src[i], v1 = src[i + stride], v2 = src[i + 2 * stride], v3 = src[i + 3 * stride];
        m0 = max(m0, u4max(v0));
        m1 = max(m1, u4max(v1));
        m2 = max(m2, u4max(v2));
        m3 = max(m3, u4max(v3));
    }
    for (; i < n4; i += stride) m0 = max(m0, u4max(src[i]));
    unsigned m = warp_max(max(max(m0, m1), max(m2, m3)));
    __shared__ unsigned s[8];
    if ((threadIdx.x & 31) == 0) s[threadIdx.x >> 5] = m;
    __syncthreads();
    if (threadIdx.x == 0) {
        unsigned b = s[0];
        #pragma unroll
        for (int j = 1; j < 8; j++) b = max(b, s[j]);
        g_part[blockIdx.y][blockIdx.x] = b;
    }
}

// Stage 2: tiny final reduce; overwrites g_amax_f (stateless).
__global__ void amax_fin_k() {
    int which = blockIdx.x;
    unsigned m = 0;
    for (int i = threadIdx.x; i < APART; i += 256) m = max(m, g_part[which][i]);
    m = warp_max(m);
    __shared__ unsigned s[8];
    if ((threadIdx.x & 31) == 0) s[threadIdx.x >> 5] = m;
    __syncthreads();
    if (threadIdx.x == 0) {
        unsigned b = s[0];
        #pragma unroll
        for (int j = 1; j < 8; j++) b = max(b, s[j]);
        g_amax_f[which] = __uint_as_float(b);
    }
}

// Quantize BOTH tensors into tiled + SW128-pre-swizzled bf16.
#define QBLKS (MROWS * KIN / 8 / 256)   // 8192 blocks per tensor
__global__ void quant2_k(const float* __restrict__ x, const float* __restrict__ w) {
    int which = blockIdx.x >= QBLKS;
    const float* src = which ? w : x;
    __nv_bfloat16* dst = which ? g_wq : g_xq;
    float scale = g_amax_f[which] / 448.0f;

    int t = (blockIdx.x - which * QBLKS) * blockDim.x + threadIdx.x;
    int row = t >> 8;
    int k   = (t & 255) << 3;
    const float4* s = (const float4*)(src + (size_t)row * KIN + k);
    float4 a = s[0], b = s[1];
    __align__(16) __nv_bfloat16 q[8];
    q[0] = __float2bfloat16(a.x / scale);
    q[1] = __float2bfloat16(a.y / scale);
    q[2] = __float2bfloat16(a.z / scale);
    q[3] = __float2bfloat16(a.w / scale);
    q[4] = __float2bfloat16(b.x / scale);
    q[5] = __float2bfloat16(b.y / scale);
    q[6] = __float2bfloat16(b.z / scale);
    q[7] = __float2bfloat16(b.w / scale);
    int rt = row >> 7, r = row & 127, kt = k >> 6, c = k & 63;
    size_t byte = (size_t)(rt * KTILES + kt) * TILE_B + SW128(r * 128 + c * 2);
    *(uint4*)((char*)dst + byte) = *(const uint4*)q;
}

// ---------------------------------------------------------------------------
// GEMM: CTA tile 128(M) x 128(N) x 64(K-chunk), 128 threads = 4 warps (2x2),
// warp tile 64x64. 3-stage ring, split-phase sync (mbarrier full / named-bar
// empty). NEW: fragment-level software pipelining -- B frags staggered one
// group ahead, A frags double-buffered across ks, so LDSM latency hides under
// mma bursts; only one exposed LDSM seam per kt. 2 CTAs/SM.
#define STAGES   3
#define STAGE_B  32768          // 16KB A + 16KB B
#define MBAR_OFF (STAGES * STAGE_B)
#define SMEM_SZ  (STAGES * STAGE_B + 32)

__global__ void __launch_bounds__(128, 2)
gemm_k(const float* __restrict__ bias, float* __restrict__ out) {
    extern __shared__ __align__(1024) char smem[];
    const uint32_t sb = smem_u32(smem);
    const uint32_t FULL = sb + MBAR_OFF;         // 3 x 8B mbarriers
    const int tid = threadIdx.x, lane = tid & 31, wid = tid >> 5;
    const int wm = wid >> 1, wn = wid & 1;           // warp grid 2(M) x 2(N)
    const int mt_blk = blockIdx.y, nt_blk = blockIdx.x;
    const int bid = blockIdx.y * gridDim.x + blockIdx.x;
    const int kt0 = (bid * 7) & (KTILES - 1);        // per-CTA K-phase rotation

    const float scale = (g_amax_f[0] / 448.0f) * (g_amax_f[1] / 448.0f);

    const char* Ab = (const char*)g_xq + (size_t)(mt_blk * KTILES) * TILE_B;
    const char* Bb = (const char*)g_wq + (size_t)(nt_blk * KTILES) * TILE_B;

    if (tid == 0) {
        #pragma unroll
        for (int s = 0; s < STAGES; s++) mbar_init(FULL + 8 * s, 128);
    }
    __syncthreads();   // barriers visible before any cp.async arrive

    auto load_stage = [&](int i /* logical iter */, int s) {
        uint32_t d = sb + s * STAGE_B;
        size_t go = (size_t)((kt0 + i) & (KTILES - 1)) * TILE_B;
        #pragma unroll
        for (int j = 0; j < 8; j++) {
            uint32_t off = tid * 16 + j * 2048;
            cp16(d + off,         Ab + go + off);
            cp16(d + 16384 + off, Bb + go + off);
        }
        cpasync_arrive(FULL + 8 * s);
    };

    // per-lane ldmatrix address components
    const int ra  = (lane & 7) + ((lane >> 3) & 1) * 8;   // A row within 16
    const int kha = (lane >> 4) * 16;                      // A k-half byte offset
    const int rb  = (lane & 7) + ((lane >> 4) & 1) * 8;   // B n within 16
    const int khb = ((lane >> 3) & 1) * 16;                // B k-half byte offset

    float acc[4][8][4];
    #pragma unroll
    for (int i = 0; i < 4; i++)
        #pragma unroll
        for (int j = 0; j < 8; j++)
            #pragma unroll
            for (int l = 0; l < 4; l++) acc[i][j][l] = 0.0f;

    load_stage(0, 0);
    load_stage(1, 1);

    int fph[STAGES] = {0, 0, 0};   // full-barrier parities per slot

    uint32_t a0[4][4], a1[4][4];   // A fragment double buffer (by ks parity)
    uint32_t bb[4][4];             // B fragments, staggered one group ahead

    for (int i = 0; i < KTILES; i++) {
        const int s = i % STAGES;
        mbar_wait(FULL + 8 * s, fph[s]); fph[s] ^= 1;

        const uint32_t dA = sb + s * STAGE_B;
        const uint32_t dB = dA + 16384;

        // seam (once per kt): a frags for ks=0 + b[0] for ks=0
        #pragma unroll
        for (int mt = 0; mt < 4; mt++) {
            uint32_t off = (uint32_t)(wm * 64 + mt * 16 + ra) * 128 + kha;
            ldsm_x4(a0[mt][0], a0[mt][1], a0[mt][2], a0[mt][3], dA + SW128(off));
        }
        {
            uint32_t off = (uint32_t)(wn * 64 + rb) * 128 + khb;
            ldsm_x4(bb[0][0], bb[0][1], bb[0][2], bb[0][3], dB + SW128(off));
        }

        #pragma unroll
        for (int ks = 0; ks < 4; ks++) {
            uint32_t (*ac)[4] = (ks & 1) ? a1 : a0;
            uint32_t (*an)[4] = (ks & 1) ? a0 : a1;
            #pragma unroll
            for (int nt = 0; nt < 4; nt++) {
                if (nt < 3) {
                    // prefetch b[nt+1] of current ks (consumed ~8 mmas later)
                    uint32_t off = (uint32_t)(wn * 64 + (nt + 1) * 16 + rb) * 128 + ks * 32 + khb;
                    ldsm_x4(bb[nt + 1][0], bb[nt + 1][1], bb[nt + 1][2], bb[nt + 1][3],
                            dB + SW128(off));
                } else if (ks < 3) {
                    // prefetch all A frags + b[0] for ks+1 (consumed next group)
                    #pragma unroll
                    for (int mt = 0; mt < 4; mt++) {
                        uint32_t off = (uint32_t)(wm * 64 + mt * 16 + ra) * 128 + (ks + 1) * 32 + kha;
                        ldsm_x4(an[mt][0], an[mt][1], an[mt][2], an[mt][3], dA + SW128(off));
                    }
                    uint32_t off = (uint32_t)(wn * 64 + rb) * 128 + (ks + 1) * 32 + khb;
                    ldsm_x4(bb[0][0], bb[0][1], bb[0][2], bb[0][3], dB + SW128(off));
                }
                #pragma unroll
                for (int mt = 0; mt < 4; mt++) {
                    mma16816(acc[mt][2 * nt],     ac[mt], bb[nt][0], bb[nt][1]);
                    mma16816(acc[mt][2 * nt + 1], ac[mt], bb[nt][2], bb[nt][3]);
                }
            }
        }
        // mma issue implies ldsm reads of slot s completed -> signal done-with-s
        nbar_arrive(1 + s);

        // refill slot (i+2)%3: pair with arrives from iteration i-1 (same slot)
        if (i + 2 < KTILES) {
            const int s2 = (i + 2) % STAGES;
            if (i + 2 >= STAGES) nbar_sync(1 + s2);
            load_stage(i + 2, s2);
        }
    }

    // epilogue: round accum to bf16 (match XLA bf16 einsum output), scale, +bias
    const int g = lane >> 2, t4 = lane & 3;

    #pragma unroll
    for (int mt = 0; mt < 4; mt++) {
        size_t r0 = (size_t)mt_blk * 128 + wm * 64 + mt * 16 + g;
        size_t r1 = r0 + 8;
        #pragma unroll
        for (int n8 = 0; n8 < 8; n8++) {
            int col = nt_blk * 128 + wn * 64 + n8 * 8 + t4 * 2;
            float2 bv = *(const float2*)(bias + col);
            float2 o0, o1;
            o0.x = __bfloat162float(__float2bfloat16(acc[mt][n8][0])) * scale + bv.x;
            o0.y = __bfloat162float(__float2bfloat16(acc[mt][n8][1])) * scale + bv.y;
            o1.x = __bfloat162float(__float2bfloat16(acc[mt][n8][2])) * scale + bv.x;
            o1.y = __bfloat162float(__float2bfloat16(acc[mt][n8][3])) * scale + bv.y;
            __stcs((float2*)(out + r0 * NOUT + col), o0);
            __stcs((float2*)(out + r1 * NOUT + col), o1);
        }
    }
}

// ---------------------------------------------------------------------------
extern "C" void kernel_launch(void* const* d_in, const int* in_sizes, int n_in,
                              void* d_out, int out_size) {
    const float* x    = (const float*)d_in[0];   // [2,4096,2048]
    const float* w    = (const float*)d_in[1];   // [8192,2048]
    const float* bias = (const float*)d_in[2];   // [8192]
    float* out = (float*)d_out;
    (void)in_sizes; (void)n_in; (void)out_size;

    amax2_k<<<dim3(APART, 2), 256>>>((const float4*)x, (const float4*)w, MROWS * KIN / 4);
    amax_fin_k<<<2, 256>>>();
    quant2_k<<<2 * QBLKS, 256>>>(x, w);

    cudaFuncSetAttribute(gemm_k, cudaFuncAttributeMaxDynamicSharedMemorySize, SMEM_SZ);
    gemm_k<<<dim3(NOUT / 128, MROWS / 128, 1), 128, SMEM_SZ>>>(bias, out);
}

// round 16
// speedup vs baseline: 1.0208x; 1.0208x over previous
#include <cuda_runtime.h>
#include <cuda_bf16.h>
#include <cstdint>

// Problem shape
#define MROWS   8192          // B*S
#define NOUT    8192
#define KIN     2048
#define KTILES  32            // KIN / 64
#define TILE_B  16384         // 128 rows * 128 bytes (64 bf16), SW128-swizzled
#define APART   1024          // amax partial blocks per tensor

// Scratch (device globals: allocation-free rule).
// g_part / g_amax_f fully overwritten every call -> stateless across replays.
__device__ unsigned       g_part[2][APART];
__device__ float          g_amax_f[2];
__device__ __nv_bfloat16  g_xq[(size_t)MROWS * KIN]; // tiled+swizzled
__device__ __nv_bfloat16  g_wq[(size_t)NOUT * KIN];  // tiled+swizzled

#define SW128(o) ((o) ^ (((o) >> 3) & 0x70))

__device__ __forceinline__ uint32_t smem_u32(const void* p) {
    uint32_t a;
    asm("{ .reg .u64 t; cvta.to.shared.u64 t, %1; cvt.u32.u64 %0, t; }" : "=r"(a) : "l"(p));
    return a;
}

__device__ __forceinline__ void mbar_init(uint32_t mbar, uint32_t cnt) {
    asm volatile("mbarrier.init.shared.b64 [%0], %1;" :: "r"(mbar), "r"(cnt) : "memory");
}
__device__ __forceinline__ void mbar_expect_tx(uint32_t mbar, uint32_t bytes) {
    asm volatile("mbarrier.arrive.expect_tx.shared.b64 _, [%0], %1;"
                 :: "r"(mbar), "r"(bytes) : "memory");
}
__device__ __forceinline__ void mbar_wait(uint32_t mbar, uint32_t parity) {
    asm volatile(
        "{\n\t.reg .pred p;\n\t"
        "WL_%=:\n\t"
        "mbarrier.try_wait.parity.shared.b64 p, [%0], %1;\n\t"
        "@!p bra WL_%=;\n\t}"
        :: "r"(mbar), "r"(parity) : "memory");
}
// bulk async copy global->shared, completion counted on mbar (TMA-lite; tiles
// are pre-swizzled contiguous blocks so no tensormap is needed)
__device__ __forceinline__ void bulk_g2s(uint32_t dst, const void* src, uint32_t bytes,
                                         uint32_t mbar) {
    asm volatile(
        "cp.async.bulk.shared::cta.global.mbarrier::complete_tx::bytes [%0], [%1], %2, [%3];"
        :: "r"(dst), "l"(src), "r"(bytes), "r"(mbar) : "memory");
}

// named-barrier producer/consumer pair (cheap rendezvous)
__device__ __forceinline__ void nbar_arrive(int id) {
    asm volatile("bar.arrive %0, 256;" :: "r"(id) : "memory");
}
__device__ __forceinline__ void nbar_sync(int id) {
    asm volatile("bar.sync %0, 256;" :: "r"(id) : "memory");
}

__device__ __forceinline__ void ldsm_x4(uint32_t& r0, uint32_t& r1, uint32_t& r2, uint32_t& r3,
                                        uint32_t addr) {
    asm volatile("ldmatrix.sync.aligned.m8n8.x4.shared.b16 {%0,%1,%2,%3}, [%4];"
                 : "=r"(r0), "=r"(r1), "=r"(r2), "=r"(r3) : "r"(addr));
}

__device__ __forceinline__ void mma16816(float* c, const uint32_t* a, uint32_t b0, uint32_t b1) {
    asm volatile(
        "mma.sync.aligned.m16n8k16.row.col.f32.bf16.bf16.f32 "
        "{%0,%1,%2,%3}, {%4,%5,%6,%7}, {%8,%9}, {%0,%1,%2,%3};"
        : "+f"(c[0]), "+f"(c[1]), "+f"(c[2]), "+f"(c[3])
        : "r"(a[0]), "r"(a[1]), "r"(a[2]), "r"(a[3]), "r"(b0), "r"(b1));
}

__device__ __forceinline__ unsigned warp_max(unsigned m) {
    #pragma unroll
    for (int o = 16; o; o >>= 1) m = max(m, __shfl_xor_sync(0xFFFFFFFFu, m, o));
    return m;
}
__device__ __forceinline__ unsigned u4max(float4 v) {
    unsigned m = max(__float_as_uint(fabsf(v.x)), __float_as_uint(fabsf(v.y)));
    m = max(m, __float_as_uint(fabsf(v.z)));
    return max(m, __float_as_uint(fabsf(v.w)));
}

// ---------------------------------------------------------------------------
// Stage 1: per-block amax partials for BOTH tensors (blockIdx.y selects).
__global__ void amax2_k(const float4* __restrict__ x, const float4* __restrict__ w, int n4) {
    const float4* src = blockIdx.y ? w : x;
    const int stride = APART * 256;
    int i = blockIdx.x * 256 + threadIdx.x;
    unsigned m0 = 0, m1 = 0, m2 = 0, m3 = 0;
    for (; i + 3 * stride < n4; i += 4 * stride) {
        float4 v0 = src[i], v1 = src[i + stride], v2 = src[i + 2 * stride], v3 = src[i + 3 * stride];
        m0 = max(m0, u4max(v0));
        m1 = max(m1, u4max(v1));
        m2 = max(m2, u4max(v2));
        m3 = max(m3, u4max(v3));
    }
    for (; i < n4; i += stride) m0 = max(m0, u4max(src[i]));
    unsigned m = warp_max(max(max(m0, m1), max(m2, m3)));
    __shared__ unsigned s[8];
    if ((threadIdx.x & 31) == 0) s[threadIdx.x >> 5] = m;
    __syncthreads();
    if (threadIdx.x == 0) {
        unsigned b = s[0];
        #pragma unroll
        for (int j = 1; j < 8; j++) b = max(b, s[j]);
        g_part[blockIdx.y][blockIdx.x] = b;
    }
}

// Stage 2: tiny final reduce; overwrites g_amax_f (stateless).
__global__ void amax_fin_k() {
    int which = blockIdx.x;
    unsigned m = 0;
    for (int i = threadIdx.x; i < APART; i += 256) m = max(m, g_part[which][i]);
    m = warp_max(m);
    __shared__ unsigned s[8];
    if ((threadIdx.x & 31) == 0) s[threadIdx.x >> 5] = m;
    __syncthreads();
    if (threadIdx.x == 0) {
        unsigned b = s[0];
        #pragma unroll
        for (int j = 1; j < 8; j++) b = max(b, s[j]);
        g_amax_f[which] = __uint_as_float(b);
    }
}

// Quantize BOTH tensors into tiled + SW128-pre-swizzled bf16.
#define QBLKS (MROWS * KIN / 8 / 256)   // 8192 blocks per tensor
__global__ void quant2_k(const float* __restrict__ x, const float* __restrict__ w) {
    int which = blockIdx.x >= QBLKS;
    const float* src = which ? w : x;
    __nv_bfloat16* dst = which ? g_wq : g_xq;
    float scale = g_amax_f[which] / 448.0f;

    int t = (blockIdx.x - which * QBLKS) * blockDim.x + threadIdx.x;
    int row = t >> 8;
    int k   = (t & 255) << 3;
    const float4* s = (const float4*)(src + (size_t)row * KIN + k);
    float4 a = s[0], b = s[1];
    __align__(16) __nv_bfloat16 q[8];
    q[0] = __float2bfloat16(a.x / scale);
    q[1] = __float2bfloat16(a.y / scale);
    q[2] = __float2bfloat16(a.z / scale);
    q[3] = __float2bfloat16(a.w / scale);
    q[4] = __float2bfloat16(b.x / scale);
    q[5] = __float2bfloat16(b.y / scale);
    q[6] = __float2bfloat16(b.z / scale);
    q[7] = __float2bfloat16(b.w / scale);
    int rt = row >> 7, r = row & 127, kt = k >> 6, c = k & 63;
    size_t byte = (size_t)(rt * KTILES + kt) * TILE_B + SW128(r * 128 + c * 2);
    *(uint4*)((char*)dst + byte) = *(const uint4*)q;
}

// ---------------------------------------------------------------------------
// GEMM: CTA tile 128(M) x 128(N) x 64(K-chunk), 128 threads = 4 warps (2x2),
// warp tile 64x64. 3-stage ring. NEW: stage fill via single-thread
// cp.async.bulk (2 x 16KB) bound to full[s] mbarrier with expect_tx -- kills
// 2048 per-CTA LDGSTS issues + per-thread copy addressing per stage. empty =
// named barrier (R13). 2 CTAs/SM; per-CTA K-phase rotation vs co-resident.
#define STAGES   3
#define STAGE_B  32768          // 16KB A + 16KB B
#define MBAR_OFF (STAGES * STAGE_B)
#define SMEM_SZ  (STAGES * STAGE_B + 32)

__global__ void __launch_bounds__(128, 2)
gemm_k(const float* __restrict__ bias, float* __restrict__ out) {
    extern __shared__ __align__(1024) char smem[];
    const uint32_t sb = smem_u32(smem);
    const uint32_t FULL = sb + MBAR_OFF;         // 3 x 8B mbarriers
    const int tid = threadIdx.x, lane = tid & 31, wid = tid >> 5;
    const int wm = wid >> 1, wn = wid & 1;           // warp grid 2(M) x 2(N)
    const int mt_blk = blockIdx.y, nt_blk = blockIdx.x;
    const int bid = blockIdx.y * gridDim.x + blockIdx.x;
    const int kt0 = (bid * 7) & (KTILES - 1);        // per-CTA K-phase rotation

    const float scale = (g_amax_f[0] / 448.0f) * (g_amax_f[1] / 448.0f);

    const char* Ab = (const char*)g_xq + (size_t)(mt_blk * KTILES) * TILE_B;
    const char* Bb = (const char*)g_wq + (size_t)(nt_blk * KTILES) * TILE_B;

    if (tid == 0) {
        #pragma unroll
        for (int s = 0; s < STAGES; s++) mbar_init(FULL + 8 * s, 1);
    }
    __syncthreads();   // barriers visible before first expect_tx/bulk

    // single-thread stage fill: arm barrier, then 2 bulk copies
    auto load_stage = [&](int i /* logical iter */, int s) {
        if (tid == 0) {
            uint32_t d = sb + s * STAGE_B;
            size_t go = (size_t)((kt0 + i) & (KTILES - 1)) * TILE_B;
            mbar_expect_tx(FULL + 8 * s, STAGE_B);
            bulk_g2s(d,         Ab + go, TILE_B, FULL + 8 * s);
            bulk_g2s(d + 16384, Bb + go, TILE_B, FULL + 8 * s);
        }
    };

    // per-lane ldmatrix address components
    const int ra  = (lane & 7) + ((lane >> 3) & 1) * 8;   // A row within 16
    const int kha = (lane >> 4) * 16;                      // A k-half byte offset
    const int rb  = (lane & 7) + ((lane >> 4) & 1) * 8;   // B n within 16
    const int khb = ((lane >> 3) & 1) * 16;                // B k-half byte offset

    float acc[4][8][4];
    #pragma unroll
    for (int i = 0; i < 4; i++)
        #pragma unroll
        for (int j = 0; j < 8; j++)
            #pragma unroll
            for (int l = 0; l < 4; l++) acc[i][j][l] = 0.0f;

    load_stage(0, 0);
    load_stage(1, 1);

    int fph[STAGES] = {0, 0, 0};   // full-barrier parities per slot

    for (int i = 0; i < KTILES; i++) {
        const int s = i % STAGES;
        mbar_wait(FULL + 8 * s, fph[s]); fph[s] ^= 1;

        const uint32_t dA = sb + s * STAGE_B;
        const uint32_t dB = dA + 16384;

        #pragma unroll
        for (int ks = 0; ks < 4; ks++) {
            uint32_t a[4][4];
            #pragma unroll
            for (int mt = 0; mt < 4; mt++) {
                uint32_t off = (uint32_t)(wm * 64 + mt * 16 + ra) * 128 + ks * 32 + kha;
                ldsm_x4(a[mt][0], a[mt][1], a[mt][2], a[mt][3], dA + SW128(off));
            }
            uint32_t b[4][4];
            #pragma unroll
            for (int nt = 0; nt < 4; nt++) {
                uint32_t off = (uint32_t)(wn * 64 + nt * 16 + rb) * 128 + ks * 32 + khb;
                ldsm_x4(b[nt][0], b[nt][1], b[nt][2], b[nt][3], dB + SW128(off));
            }
            #pragma unroll
            for (int mt = 0; mt < 4; mt++)
                #pragma unroll
                for (int nt = 0; nt < 4; nt++) {
                    mma16816(acc[mt][2 * nt],     a[mt], b[nt][0], b[nt][1]);
                    mma16816(acc[mt][2 * nt + 1], a[mt], b[nt][2], b[nt][3]);
                }
        }
        // mma issue implies ldsm reads of slot s completed -> signal done-with-s
        nbar_arrive(1 + s);

        // refill slot (i+2)%3: sync pairs with arrives from iteration i-1
        if (i + 2 < KTILES) {
            const int s2 = (i + 2) % STAGES;
            if (i + 2 >= STAGES) nbar_sync(1 + s2);
            load_stage(i + 2, s2);
        }
    }

    // epilogue: round accum to bf16 (match XLA bf16 einsum output), scale, +bias
    const int g = lane >> 2, t4 = lane & 3;

    #pragma unroll
    for (int mt = 0; mt < 4; mt++) {
        size_t r0 = (size_t)mt_blk * 128 + wm * 64 + mt * 16 + g;
        size_t r1 = r0 + 8;
        #pragma unroll
        for (int n8 = 0; n8 < 8; n8++) {
            int col = nt_blk * 128 + wn * 64 + n8 * 8 + t4 * 2;
            float2 bv = *(const float2*)(bias + col);
            float2 o0, o1;
            o0.x = __bfloat162float(__float2bfloat16(acc[mt][n8][0])) * scale + bv.x;
            o0.y = __bfloat162float(__float2bfloat16(acc[mt][n8][1])) * scale + bv.y;
            o1.x = __bfloat162float(__float2bfloat16(acc[mt][n8][2])) * scale + bv.x;
            o1.y = __bfloat162float(__float2bfloat16(acc[mt][n8][3])) * scale + bv.y;
            __stcs((float2*)(out + r0 * NOUT + col), o0);
            __stcs((float2*)(out + r1 * NOUT + col), o1);
        }
    }
}

// ---------------------------------------------------------------------------
extern "C" void kernel_launch(void* const* d_in, const int* in_sizes, int n_in,
                              void* d_out, int out_size) {
    const float* x    = (const float*)d_in[0];   // [2,4096,2048]
    const float* w    = (const float*)d_in[1];   // [8192,2048]
    const float* bias = (const float*)d_in[2];   // [8192]
    float* out = (float*)d_out;
    (void)in_sizes; (void)n_in; (void)out_size;

    amax2_k<<<dim3(APART, 2), 256>>>((const float4*)x, (const float4*)w, MROWS * KIN / 4);
    amax_fin_k<<<2, 256>>>();
    quant2_k<<<2 * QBLKS, 256>>>(x, w);

    cudaFuncSetAttribute(gemm_k, cudaFuncAttributeMaxDynamicSharedMemorySize, SMEM_SZ);
    gemm_k<<<dim3(NOUT / 128, MROWS / 128, 1), 128, SMEM_SZ>>>(bias, out);
}